// round 17
// baseline (speedup 1.0000x reference)
#include <cuda_runtime.h>
#include <cuda_bf16.h>

// ---------------------------------------------------------------------------
// HashEncoder (instant-ngp style), GB300 sm_103a
//   B points (x,y,z in [0,1]) -> [B, 16 levels * 2 feats] fp32
//   All 16 levels take the spatial-hash path (table sizes rounded down to 8).
//
// R16: R14 champion (290.9us; __stcs writeback kept) + ALU diet on the
//      load-issue path:
//        - hoist the 4 (hy^hz) combos (each used by 2 corners)
//        - even-gx arm computes ONLY the 4 even-corner indices it loads;
//          odd-corner indices are built only inside the odd arm
//      Indices bit-identical to the reference.
// ---------------------------------------------------------------------------

#define TP       16          // points per block
#define NLEVELS  16
#define NTHREADS (TP * NLEVELS)   // 256

__constant__ unsigned c_off[NLEVELS] = {
    0u,        4912u,     40848u,    315472u,
    839760u,   1364048u,  1888336u,  2412624u,
    2936912u,  3461200u,  3985488u,  4509776u,
    5034064u,  5558352u,  6082640u,  6606928u
};

// group g -> level: warp w (groups 2w, 2w+1) gets levels {w, 15-w}
__constant__ unsigned char c_perm[NLEVELS] = {
    0, 15, 1, 14, 2, 13, 3, 12, 4, 11, 5, 10, 6, 9, 7, 8
};

__global__ __launch_bounds__(NTHREADS)
void hash_encoder_kernel(const float* __restrict__ xyz,
                         const float2* __restrict__ emb,
                         float2* __restrict__ out)
{
    __shared__ float  sxyz[TP * 3];
    __shared__ float2 sres[TP][NLEVELS + 1];   // +1 pad: conflict-free transpose

    const unsigned tid   = threadIdx.x;
    const unsigned level = c_perm[tid >> 4];   // balanced warp pairing
    const unsigned p     = tid & 15u;          // point within block
    const unsigned base  = blockIdx.x * TP;

    // stage this block's 16 points (48 floats), coalesced; B % TP == 0
    if (tid < TP * 3) {
        sxyz[tid] = xyz[base * 3u + tid];
    }
    __syncthreads();

    const float x = sxyz[p * 3u + 0];
    const float y = sxyz[p * 3u + 1];
    const float z = sxyz[p * 3u + 2];

    // scale = exp2(level)*16 - 1  (exact in fp32)
    const float scale = (float)(16u << level) - 1.0f;

    const float px = fmaf(x, scale, 0.5f);
    const float py = fmaf(y, scale, 0.5f);
    const float pz = fmaf(z, scale, 0.5f);
    const float gx_f = floorf(px), gy_f = floorf(py), gz_f = floorf(pz);
    const float fx = px - gx_f, fy = py - gy_f, fz = pz - gz_f;
    const unsigned gx = (unsigned)gx_f;
    const unsigned gy = (unsigned)gy_f;
    const unsigned gz = (unsigned)gz_f;

    // spatial hash components: idx = gx' ^ (gy'*2654435761) ^ (gz'*805459861)
    const unsigned hy0 = gy * 2654435761u;
    const unsigned hy1 = hy0 + 2654435761u;
    const unsigned hz0 = gz * 805459861u;
    const unsigned hz1 = hz0 + 805459861u;

    // hoist the 4 yz combos (each feeds two corners)
    const unsigned yz00 = hy0 ^ hz0;
    const unsigned yz10 = hy1 ^ hz0;
    const unsigned yz01 = hy0 ^ hz1;
    const unsigned yz11 = hy1 ^ hz1;

    // even-x corner indices (always needed)
    unsigned e0 = gx ^ yz00;   // corner (0,0,0)
    unsigned e1 = gx ^ yz10;   // corner (0,1,0)
    unsigned e2 = gx ^ yz01;   // corner (0,0,1)
    unsigned e3 = gx ^ yz11;   // corner (0,1,1)

    const float2* __restrict__ tab = emb + c_off[level];
    float2 v[8];   // order: [e0,o0, e1,o1, e2,o2, e3,o3] = corner pairs in x

    if (level >= 3) {
        e0 &= 524287u; e1 &= 524287u; e2 &= 524287u; e3 &= 524287u;

        if ((gx & 1u) == 0u) {
            // gx even -> odd-x mate == e^1: aligned {2k,2k+1} float4.
            // 4x LDG.128, no odd-index math at all.
            const unsigned ei[4] = { e0, e1, e2, e3 };
            #pragma unroll
            for (int pr = 0; pr < 4; pr++) {
                const unsigned i0 = ei[pr];
                const float4 q = __ldg((const float4*)(tab + (i0 & ~1u)));
                const float2 lo = make_float2(q.x, q.y);
                const float2 hi = make_float2(q.z, q.w);
                const bool o = (i0 & 1u) != 0u;
                v[2 * pr]     = o ? hi : lo;
                v[2 * pr + 1] = o ? lo : hi;
            }
        } else {
            const unsigned gx1 = gx + 1u;
            unsigned oi[4];
            oi[0] = (gx1 ^ yz00) & 524287u;
            oi[1] = (gx1 ^ yz10) & 524287u;
            oi[2] = (gx1 ^ yz01) & 524287u;
            oi[3] = (gx1 ^ yz11) & 524287u;
            v[0] = __ldg(&tab[e0]);  v[1] = __ldg(&tab[oi[0]]);
            v[2] = __ldg(&tab[e1]);  v[3] = __ldg(&tab[oi[1]]);
            v[4] = __ldg(&tab[e2]);  v[5] = __ldg(&tab[oi[2]]);
            v[6] = __ldg(&tab[e3]);  v[7] = __ldg(&tab[oi[3]]);
        }
    } else {
        // non-power-of-2 tables: magic-mul modulo, separate gathers
        const unsigned gx1 = gx + 1u;
        unsigned o0 = gx1 ^ yz00, o1 = gx1 ^ yz10,
                 o2 = gx1 ^ yz01, o3 = gx1 ^ yz11;
        if (level == 2) {
            e0 %= 274624u; o0 %= 274624u; e1 %= 274624u; o1 %= 274624u;
            e2 %= 274624u; o2 %= 274624u; e3 %= 274624u; o3 %= 274624u;
        } else if (level == 1) {
            e0 %= 35936u;  o0 %= 35936u;  e1 %= 35936u;  o1 %= 35936u;
            e2 %= 35936u;  o2 %= 35936u;  e3 %= 35936u;  o3 %= 35936u;
        } else {
            e0 %= 4912u;   o0 %= 4912u;   e1 %= 4912u;   o1 %= 4912u;
            e2 %= 4912u;   o2 %= 4912u;   e3 %= 4912u;   o3 %= 4912u;
        }
        v[0] = __ldg(&tab[e0]);  v[1] = __ldg(&tab[o0]);
        v[2] = __ldg(&tab[e1]);  v[3] = __ldg(&tab[o1]);
        v[4] = __ldg(&tab[e2]);  v[5] = __ldg(&tab[o2]);
        v[6] = __ldg(&tab[e3]);  v[7] = __ldg(&tab[o3]);
    }

    // weights in matching pair order: v[2k]=even-x corner, v[2k+1]=odd-x
    const float wx0 = 1.0f - fx, wy0 = 1.0f - fy, wz0 = 1.0f - fz;
    float w[8];
    w[0] = (wx0 * wy0) * wz0;   // (0,0,0)
    w[1] = (fx  * wy0) * wz0;   // (1,0,0)
    w[2] = (wx0 * fy ) * wz0;   // (0,1,0)
    w[3] = (fx  * fy ) * wz0;   // (1,1,0)
    w[4] = (wx0 * wy0) * fz;    // (0,0,1)
    w[5] = (fx  * wy0) * fz;    // (1,0,1)
    w[6] = (wx0 * fy ) * fz;    // (0,1,1)
    w[7] = (fx  * fy ) * fz;    // (1,1,1)
    // v pair order is [ (0,0,0)(1,0,0) (0,1,0)(1,1,0) (0,0,1)(1,0,1) (0,1,1)(1,1,1) ]
    // which matches w[0..7] exactly.

    float rx = 0.0f, ry = 0.0f;
    #pragma unroll
    for (int c = 0; c < 8; c++) {
        rx = fmaf(w[c], v[c].x, rx);
        ry = fmaf(w[c], v[c].y, ry);
    }

    sres[p][level] = make_float2(rx, ry);
    __syncthreads();

    // coalesced, streaming writeback (output never re-read)
    const unsigned pp = tid >> 4;
    const unsigned ll = tid & 15u;
    __stcs(&out[base * NLEVELS + tid], sres[pp][ll]);
}

extern "C" void kernel_launch(void* const* d_in, const int* in_sizes, int n_in,
                              void* d_out, int out_size)
{
    const float*  xyz = (const float*)d_in[0];
    const float2* emb = (const float2*)d_in[1];
    // d_in[2] = normalize flag (0) -> raw coordinates path; ignored.

    const int B = in_sizes[0] / 3;       // 1048576; multiple of TP
    const int blocks = B / TP;

    hash_encoder_kernel<<<blocks, NTHREADS>>>(xyz, emb, (float2*)d_out);
}